// round 16
// baseline (speedup 1.0000x reference)
#include <cuda_runtime.h>
#include <cuda_fp16.h>
#include <math.h>
#include <stdint.h>

#define T 1024
#define H 1024
#define FF 2048
#define E 8
#define KSEL 2
#define NSLOT (T * KSEL)   // 2048
#define NK1 (H / 64)       // 16 k-chunks gemm1
#define NK2 (FF / 64)      // 32 k-chunks gemm2

// ---------------- scratch (device globals: allocation-free) ----------------
__device__ int   g_count[E];
__device__ int   g_offset[E];
__device__ int   g_tok[NSLOT];
__device__ float g_scale[NSLOT];
__device__ __half g_hh[(size_t)T * H];            // 2MB   fp16 hidden
__device__ __half g_acth[(size_t)NSLOT * FF];     // 8MB   fp16 act
__device__ __half g_w1h[(size_t)E * 2 * FF * H];  // 67MB  fp16 w1

// ---------------- helpers ----------------
__device__ __forceinline__ uint32_t s2u(const void* p) {
    return (uint32_t)__cvta_generic_to_shared(p);
}
__device__ __forceinline__ void ldsm4(uint32_t (&r)[4], uint32_t addr) {
    asm volatile("ldmatrix.sync.aligned.m8n8.x4.shared.b16 {%0,%1,%2,%3}, [%4];"
                 : "=r"(r[0]), "=r"(r[1]), "=r"(r[2]), "=r"(r[3]) : "r"(addr));
}
__device__ __forceinline__ void mma16816(float (&c)[4], const uint32_t (&a)[4],
                                         const uint32_t* b) {
    asm volatile(
        "mma.sync.aligned.m16n8k16.row.col.f32.f16.f16.f32 "
        "{%0,%1,%2,%3},{%4,%5,%6,%7},{%8,%9},{%0,%1,%2,%3};"
        : "+f"(c[0]), "+f"(c[1]), "+f"(c[2]), "+f"(c[3])
        : "r"(a[0]), "r"(a[1]), "r"(a[2]), "r"(a[3]), "r"(b[0]), "r"(b[1]));
}
__device__ __forceinline__ uint2 cvt4(const float4& v) {
    __half2 a = __floats2half2_rn(v.x, v.y);
    __half2 b = __floats2half2_rn(v.z, v.w);
    return make_uint2(*(uint32_t*)&a, *(uint32_t*)&b);
}

#define ROW_S 144   // 128B data + 16B pad: conflict-free ldmatrix + STS

// ---------------- fused route (blocks 0..7) + w1/hidden prep (rest) --------
#define N4H  (T * H / 4)
#define N4W1 (E * 2 * FF * H / 4)
#define N4P  (N4H + N4W1)
#define PREP_BLOCKS ((N4P + 255) / 256)

__global__ void route_prep(const int* __restrict__ sel,
                           const float* __restrict__ scales,
                           const float* __restrict__ hidden,
                           const float* __restrict__ w1,
                           __half* __restrict__ dh,
                           __half* __restrict__ dw1) {
    const int tid = threadIdx.x;
    if (blockIdx.x < E) {
        const int e = blockIdx.x;
        __shared__ int s_cnt[E];
        __shared__ int s_base, s_cur;
        if (tid < E) s_cnt[tid] = 0;
        if (tid == 0) s_cur = 0;
        __syncthreads();
        for (int i = tid; i < NSLOT; i += blockDim.x)
            atomicAdd(&s_cnt[sel[i]], 1);
        __syncthreads();
        if (tid == 0) {
            int off = 0;
            for (int k = 0; k < e; k++) off += s_cnt[k];
            g_offset[e] = off;
            g_count[e]  = s_cnt[e];
            s_base = off;
        }
        __syncthreads();
        const int base = s_base;
        for (int i = tid; i < NSLOT; i += blockDim.x) {
            if (sel[i] == e) {
                int pos = base + atomicAdd(&s_cur, 1);
                g_tok[pos]   = i / KSEL;
                g_scale[pos] = scales[i];
            }
        }
        return;
    }
    int i4 = (blockIdx.x - E) * blockDim.x + tid;
    const float* src;
    __half* dst;
    if (i4 < N4W1)            { src = w1; dst = dw1; }
    else if (i4 < N4W1 + N4H) { i4 -= N4W1; src = hidden; dst = dh; }
    else return;
    float4 v = ((const float4*)src)[i4];
    uint2 o = cvt4(v);
    ((uint2*)dst)[i4] = o;
}

// ---------------- GEMM1: act = silu(X*W1g+b) * (X*W1l+b) -------------------
// CTA: M=64, Ngate=64, Nlin=64, k-chunk=64, 256 threads (8 warps 2Mx4N).
#define G1_BOFF (64 * ROW_S)               // 9216 (A region: 64 rows)
#define G1_STG  (G1_BOFF + 128 * ROW_S)    // 27648 per stage

__global__ __launch_bounds__(256, 2)
void gemm1_kernel(const float* __restrict__ b1) {
    const int e   = blockIdx.y;
    const int cnt = g_count[e];
    const int m0  = blockIdx.z * 64;
    if (m0 >= cnt) return;
    const int n0  = blockIdx.x * 64;
    const int off = g_offset[e];

    extern __shared__ char sm[];
    __shared__ float s_bg[64], s_bl[64];

    const int tid = threadIdx.x, lane = tid & 31, wid = tid >> 5;
    const int wm = wid & 1, wn = wid >> 1;

    if (tid < 64)       s_bg[tid]      = b1[(size_t)e * 2 * FF + n0 + tid];
    else if (tid < 128) s_bl[tid - 64] = b1[(size_t)e * 2 * FF + FF + n0 + tid - 64];

    // A staging: 64 rows x 128B; 4 thr/row x 32B (2x uint4)
    const int arow = tid >> 2, acol = (tid & 3) * 32;
    const int mrow = m0 + arow;
    const int slot = off + (mrow < cnt ? mrow : cnt - 1);
    const unsigned char* srcA =
        (const unsigned char*)(g_hh + (size_t)g_tok[slot] * H) + acol;
    const uint32_t dAo = (uint32_t)arow * ROW_S + acol;

    // B staging: 128 rows (64 gate + 64 lin) x 128B; 2 thr/row x 64B
    const int brow = tid >> 1, bhalf = (tid & 1) * 64;
    const int bchan = (brow < 64) ? (e * 2 * FF + n0 + brow)
                                  : (e * 2 * FF + FF + n0 + (brow - 64));
    const unsigned char* srcB =
        (const unsigned char*)(g_w1h + (size_t)bchan * H) + bhalf;
    const uint32_t dBo = G1_BOFF + (uint32_t)brow * ROW_S + bhalf;

    // ldmatrix bases
    const uint32_t smb = s2u(sm);
    const uint32_t laA = (uint32_t)((lane & 15) + wm * 32) * ROW_S + (lane >> 4) * 16;
    const uint32_t lbB = G1_BOFF +
        (uint32_t)(wn * 16 + ((lane >> 4) & 1) * 8 + (lane & 7)) * ROW_S +
        ((lane >> 3) & 1) * 16;

    float cg[2][2][4] = {}, cl[2][2][4] = {};
    uint4 ra[2], rb[4];

#pragma unroll
    for (int q = 0; q < 2; q++) ra[q] = *(const uint4*)(srcA + q * 16);
#pragma unroll
    for (int q = 0; q < 4; q++) rb[q] = *(const uint4*)(srcB + q * 16);

    for (int kt = 0; kt < NK1; kt++) {
        char* bb = sm + (kt & 1) * G1_STG;
#pragma unroll
        for (int q = 0; q < 2; q++) *(uint4*)(bb + dAo + q * 16) = ra[q];
#pragma unroll
        for (int q = 0; q < 4; q++) *(uint4*)(bb + dBo + q * 16) = rb[q];

        if (kt + 1 < NK1) {
            const unsigned char* sa = srcA + (size_t)(kt + 1) * 128;
            const unsigned char* sb = srcB + (size_t)(kt + 1) * 128;
#pragma unroll
            for (int q = 0; q < 2; q++) ra[q] = *(const uint4*)(sa + q * 16);
#pragma unroll
            for (int q = 0; q < 4; q++) rb[q] = *(const uint4*)(sb + q * 16);
        }
        __syncthreads();

        const uint32_t bbu = smb + (kt & 1) * G1_STG;
#pragma unroll
        for (int kk = 0; kk < 4; kk++) {
            uint32_t ah[2][4];
#pragma unroll
            for (int i = 0; i < 2; i++)
                ldsm4(ah[i], bbu + laA + i * (16 * ROW_S) + kk * 32);
            uint32_t bg4[4], bl4[4];
            ldsm4(bg4, bbu + lbB + kk * 32);
            ldsm4(bl4, bbu + lbB + 64 * ROW_S + kk * 32);
#pragma unroll
            for (int i = 0; i < 2; i++) {
                mma16816(cg[i][0], ah[i], &bg4[0]);
                mma16816(cg[i][1], ah[i], &bg4[2]);
                mma16816(cl[i][0], ah[i], &bl4[0]);
                mma16816(cl[i][1], ah[i], &bl4[2]);
            }
        }
        __syncthreads();
    }

    // epilogue: bias + silu(gate)*lin; store act as fp16 pairs
#pragma unroll
    for (int i = 0; i < 2; i++)
#pragma unroll
        for (int rr = 0; rr < 2; rr++) {
            const int m = wm * 32 + i * 16 + (lane >> 2) + rr * 8 + m0;
            if (m >= cnt) continue;
            __half* actrow = g_acth + (size_t)(off + m) * FF;
#pragma unroll
            for (int j = 0; j < 2; j++) {
                const int c = wn * 16 + j * 8 + (lane & 3) * 2;
                float r0, r1;
#pragma unroll
                for (int q = 0; q < 2; q++) {
                    const int idx = rr * 2 + q;
                    const float g = cg[i][j][idx] + s_bg[c + q];
                    const float l = cl[i][j][idx] + s_bl[c + q];
                    const float r = g * l / (1.0f + __expf(-g));
                    if (q == 0) r0 = r; else r1 = r;
                }
                __half2 hv = __floats2half2_rn(r0, r1);
                *(uint32_t*)(actrow + n0 + c) = *(uint32_t*)&hv;
            }
        }
}

// ---------------- GEMM2: out += scale*(act*W2^T + b2) ----------------------
// CTA: M=64, N=128 over H, k-chunk=64, 256 threads (8 warps 2Mx4N).
// B loaded as fp32 directly from w2, converted to fp16 in-register at STS.
#define G2_BOFF (64 * ROW_S)               // 9216
#define G2_STG  (G2_BOFF + 128 * ROW_S)    // 27648 per stage

__global__ __launch_bounds__(256, 2)
void gemm2_kernel(const float* __restrict__ w2, const float* __restrict__ b2,
                  float* __restrict__ out) {
    const int e   = blockIdx.y;
    const int cnt = g_count[e];
    const int m0  = blockIdx.z * 64;
    if (m0 >= cnt) return;
    const int n0  = blockIdx.x * 128;
    const int off = g_offset[e];

    extern __shared__ char sm[];
    __shared__ float s_b2[128];

    const int tid = threadIdx.x, lane = tid & 31, wid = tid >> 5;
    const int wm = wid & 1, wn = wid >> 1;

    if (tid < 128) s_b2[tid] = b2[(size_t)e * H + n0 + tid];

    // A staging: 64 rows x 128B; 4 thr/row x 32B
    const int arow = tid >> 2, acol = (tid & 3) * 32;
    const int mrow = m0 + arow;
    const unsigned char* srcA =
        (const unsigned char*)(g_acth +
            (size_t)(off + (mrow < cnt ? mrow : cnt - 1)) * FF) + acol;
    const uint32_t dAo = (uint32_t)arow * ROW_S + acol;

    // B staging: 128 rows x 64 fp32 k-values; 2 thr/row x 32 floats (128B)
    const int brow = tid >> 1, bhalf = (tid & 1) * 32;   // float offset
    const float* srcB = w2 + (size_t)(e * H + n0 + brow) * FF + bhalf;
    const uint32_t dBo = G2_BOFF + (uint32_t)brow * ROW_S + bhalf * 2;

    const uint32_t smb = s2u(sm);
    const uint32_t laA = (uint32_t)((lane & 15) + wm * 32) * ROW_S + (lane >> 4) * 16;
    const uint32_t lbB = G2_BOFF +
        (uint32_t)(wn * 32 + ((lane >> 4) & 1) * 8 + (lane & 7)) * ROW_S +
        ((lane >> 3) & 1) * 16;

    float c[2][4][4] = {};
    uint4 ra[2];
    float4 rb[8];

#pragma unroll
    for (int q = 0; q < 2; q++) ra[q] = *(const uint4*)(srcA + q * 16);
#pragma unroll
    for (int q = 0; q < 8; q++) rb[q] = *(const float4*)(srcB + q * 4);

    for (int kt = 0; kt < NK2; kt++) {
        char* bb = sm + (kt & 1) * G2_STG;
#pragma unroll
        for (int q = 0; q < 2; q++) *(uint4*)(bb + dAo + q * 16) = ra[q];
#pragma unroll
        for (int q = 0; q < 4; q++) {
            uint2 lo = cvt4(rb[q * 2]);
            uint2 hi = cvt4(rb[q * 2 + 1]);
            *(uint4*)(bb + dBo + q * 16) = make_uint4(lo.x, lo.y, hi.x, hi.y);
        }

        if (kt + 1 < NK2) {
            const unsigned char* sa = srcA + (size_t)(kt + 1) * 128;
            const float* sb = srcB + (size_t)(kt + 1) * 64;
#pragma unroll
            for (int q = 0; q < 2; q++) ra[q] = *(const uint4*)(sa + q * 16);
#pragma unroll
            for (int q = 0; q < 8; q++) rb[q] = *(const float4*)(sb + q * 4);
        }
        __syncthreads();

        const uint32_t bbu = smb + (kt & 1) * G2_STG;
#pragma unroll
        for (int kk = 0; kk < 4; kk++) {
            uint32_t ah[2][4];
#pragma unroll
            for (int i = 0; i < 2; i++)
                ldsm4(ah[i], bbu + laA + i * (16 * ROW_S) + kk * 32);
            uint32_t bhA[4], bhB[4];
            ldsm4(bhA, bbu + lbB + kk * 32);
            ldsm4(bhB, bbu + lbB + 16 * ROW_S + kk * 32);
#pragma unroll
            for (int i = 0; i < 2; i++) {
                mma16816(c[i][0], ah[i], &bhA[0]);
                mma16816(c[i][1], ah[i], &bhA[2]);
                mma16816(c[i][2], ah[i], &bhB[0]);
                mma16816(c[i][3], ah[i], &bhB[2]);
            }
        }
        __syncthreads();
    }

    // epilogue: scaled atomic scatter
#pragma unroll
    for (int i = 0; i < 2; i++)
#pragma unroll
        for (int rr = 0; rr < 2; rr++) {
            const int m = wm * 32 + i * 16 + (lane >> 2) + rr * 8 + m0;
            if (m >= cnt) continue;
            const int   sl  = off + m;
            const int   tok = g_tok[sl];
            const float sc  = g_scale[sl];
#pragma unroll
            for (int j = 0; j < 4; j++) {
                const int cc = wn * 32 + j * 8 + (lane & 3) * 2;
                atomicAdd(&out[(size_t)tok * H + n0 + cc],
                          sc * (c[i][j][rr * 2 + 0] + s_b2[cc]));
                atomicAdd(&out[(size_t)tok * H + n0 + cc + 1],
                          sc * (c[i][j][rr * 2 + 1] + s_b2[cc + 1]));
            }
        }
}

// ---------------- launch ----------------
extern "C" void kernel_launch(void* const* d_in, const int* in_sizes, int n_in,
                              void* d_out, int out_size) {
    const float* hidden = (const float*)d_in[0];
    const int*   sel    = (const int*)d_in[1];
    const float* scales = (const float*)d_in[2];
    const float* w1     = (const float*)d_in[3];
    const float* b1     = (const float*)d_in[4];
    const float* w2     = (const float*)d_in[5];
    const float* b2     = (const float*)d_in[6];

    void *p_hh, *p_w1h;
    cudaGetSymbolAddress(&p_hh,  g_hh);
    cudaGetSymbolAddress(&p_w1h, g_w1h);

    const int smem1 = 2 * G1_STG;   // 55296
    const int smem2 = 2 * G2_STG;   // 55296
    cudaFuncSetAttribute(gemm1_kernel, cudaFuncAttributeMaxDynamicSharedMemorySize, smem1);
    cudaFuncSetAttribute(gemm2_kernel, cudaFuncAttributeMaxDynamicSharedMemorySize, smem2);

    cudaMemsetAsync(d_out, 0, (size_t)T * H * sizeof(float), 0);

    route_prep<<<E + PREP_BLOCKS, 256>>>(sel, scales, hidden, w1,
                                         (__half*)p_hh, (__half*)p_w1h);

    dim3 g1(FF / 64, E, NSLOT / 64);    // 32 x 8 x 32
    gemm1_kernel<<<g1, 256, smem1>>>(b1);

    dim3 g2(H / 128, E, NSLOT / 64);    // 8 x 8 x 32
    gemm2_kernel<<<g2, 256, smem2>>>(w2, b2, (float*)d_out);
}

// round 17
// speedup vs baseline: 1.1829x; 1.1829x over previous
#include <cuda_runtime.h>
#include <cuda_fp16.h>
#include <math.h>
#include <stdint.h>

#define T 1024
#define H 1024
#define FF 2048
#define E 8
#define KSEL 2
#define NSLOT (T * KSEL)   // 2048
#define NK1 (H / 64)       // 16 k-chunks gemm1
#define NK2 (FF / 64)      // 32 k-chunks gemm2

// ---------------- scratch (device globals: allocation-free) ----------------
__device__ int   g_count[E];
__device__ int   g_offset[E];
__device__ int   g_tok[NSLOT];
__device__ float g_scale[NSLOT];
__device__ __half g_hh[(size_t)T * H];            // 2MB   fp16 hidden
__device__ __half g_acth[(size_t)NSLOT * FF];     // 8MB   fp16 act
__device__ __half g_w1h[(size_t)E * 2 * FF * H];  // 67MB  fp16 w1
__device__ __half g_w2h[(size_t)E * H * FF];      // 33.5MB fp16 w2

// ---------------- helpers ----------------
__device__ __forceinline__ uint32_t s2u(const void* p) {
    return (uint32_t)__cvta_generic_to_shared(p);
}
__device__ __forceinline__ void ldsm4(uint32_t (&r)[4], uint32_t addr) {
    asm volatile("ldmatrix.sync.aligned.m8n8.x4.shared.b16 {%0,%1,%2,%3}, [%4];"
                 : "=r"(r[0]), "=r"(r[1]), "=r"(r[2]), "=r"(r[3]) : "r"(addr));
}
__device__ __forceinline__ void mma16816(float (&c)[4], const uint32_t (&a)[4],
                                         const uint32_t* b) {
    asm volatile(
        "mma.sync.aligned.m16n8k16.row.col.f32.f16.f16.f32 "
        "{%0,%1,%2,%3},{%4,%5,%6,%7},{%8,%9},{%0,%1,%2,%3};"
        : "+f"(c[0]), "+f"(c[1]), "+f"(c[2]), "+f"(c[3])
        : "r"(a[0]), "r"(a[1]), "r"(a[2]), "r"(a[3]), "r"(b[0]), "r"(b[1]));
}
__device__ __forceinline__ uint2 cvt4(const float4& v) {
    __half2 a = __floats2half2_rn(v.x, v.y);
    __half2 b = __floats2half2_rn(v.z, v.w);
    return make_uint2(*(uint32_t*)&a, *(uint32_t*)&b);
}

#define ROW_S 144   // 128B data + 16B pad: conflict-free ldmatrix + STS

// ---------------- fused route (blocks 0..7) + w1/hidden prep (rest) --------
#define N4H  (T * H / 4)
#define N4W1 (E * 2 * FF * H / 4)
#define N4W2 (E * H * FF / 4)
#define N4P  (N4H + N4W1)
#define PREP_BLOCKS ((N4P + 255) / 256)

__global__ void route_prep(const int* __restrict__ sel,
                           const float* __restrict__ scales,
                           const float* __restrict__ hidden,
                           const float* __restrict__ w1,
                           __half* __restrict__ dh,
                           __half* __restrict__ dw1) {
    const int tid = threadIdx.x;
    if (blockIdx.x < E) {
        const int e = blockIdx.x;
        __shared__ int s_cnt[E];
        __shared__ int s_base, s_cur;
        if (tid < E) s_cnt[tid] = 0;
        if (tid == 0) s_cur = 0;
        __syncthreads();
        for (int i = tid; i < NSLOT; i += blockDim.x)
            atomicAdd(&s_cnt[sel[i]], 1);
        __syncthreads();
        if (tid == 0) {
            int off = 0;
            for (int k = 0; k < e; k++) off += s_cnt[k];
            g_offset[e] = off;
            g_count[e]  = s_cnt[e];
            s_base = off;
        }
        __syncthreads();
        const int base = s_base;
        for (int i = tid; i < NSLOT; i += blockDim.x) {
            if (sel[i] == e) {
                int pos = base + atomicAdd(&s_cur, 1);
                g_tok[pos]   = i / KSEL;
                g_scale[pos] = scales[i];
            }
        }
        return;
    }
    int i4 = (blockIdx.x - E) * blockDim.x + tid;
    const float* src;
    __half* dst;
    if (i4 < N4W1)            { src = w1; dst = dw1; }
    else if (i4 < N4W1 + N4H) { i4 -= N4W1; src = hidden; dst = dh; }
    else return;
    float4 v = ((const float4*)src)[i4];
    uint2 o = cvt4(v);
    ((uint2*)dst)[i4] = o;
}

// ---------------- GEMM1: act = silu(X*W1g+b) * (X*W1l+b) -------------------
// CTA: M=64, Ngate=64, Nlin=64, k-chunk=64, 256 threads (8 warps 2Mx4N).
// Blocks with z<4 also convert a static 16KB-x-16 slice of w2 (fp32->fp16),
// one float4 per thread per k-iter, filling latency bubbles.
#define G1_BOFF (64 * ROW_S)               // 9216 (A region: 64 rows)
#define G1_STG  (G1_BOFF + 128 * ROW_S)    // 27648 per stage

__global__ __launch_bounds__(256, 2)
void gemm1_kernel(const float* __restrict__ b1, const float* __restrict__ w2) {
    const int e   = blockIdx.y;
    const int cnt = g_count[e];
    const int m0  = blockIdx.z * 64;
    const int tid = threadIdx.x;

    // static w2-conversion assignment: blocks with z<4 own job (y*32+x)*4+z
    const bool doCvt = (blockIdx.z < 4);
    const int  cvtBase = doCvt
        ? (((int)blockIdx.y * 32 + (int)blockIdx.x) * 4 + (int)blockIdx.z) * 4096 + tid
        : 0;

    if (m0 >= cnt) {
        if (doCvt) {
#pragma unroll 4
            for (int kt = 0; kt < NK1; kt++) {
                const int i4 = cvtBase + kt * 256;
                float4 v = ((const float4*)w2)[i4];
                ((uint2*)g_w2h)[i4] = cvt4(v);
            }
        }
        return;
    }

    const int n0  = blockIdx.x * 64;
    const int off = g_offset[e];

    extern __shared__ char sm[];
    __shared__ float s_bg[64], s_bl[64];

    const int lane = tid & 31, wid = tid >> 5;
    const int wm = wid & 1, wn = wid >> 1;

    if (tid < 64)       s_bg[tid]      = b1[(size_t)e * 2 * FF + n0 + tid];
    else if (tid < 128) s_bl[tid - 64] = b1[(size_t)e * 2 * FF + FF + n0 + tid - 64];

    // A staging: 64 rows x 128B; 4 thr/row x 32B (2x uint4)
    const int arow = tid >> 2, acol = (tid & 3) * 32;
    const int mrow = m0 + arow;
    const int slot = off + (mrow < cnt ? mrow : cnt - 1);
    const unsigned char* srcA =
        (const unsigned char*)(g_hh + (size_t)g_tok[slot] * H) + acol;
    const uint32_t dAo = (uint32_t)arow * ROW_S + acol;

    // B staging: 128 rows (64 gate + 64 lin) x 128B; 2 thr/row x 64B
    const int brow = tid >> 1, bhalf = (tid & 1) * 64;
    const int bchan = (brow < 64) ? (e * 2 * FF + n0 + brow)
                                  : (e * 2 * FF + FF + n0 + (brow - 64));
    const unsigned char* srcB =
        (const unsigned char*)(g_w1h + (size_t)bchan * H) + bhalf;
    const uint32_t dBo = G1_BOFF + (uint32_t)brow * ROW_S + bhalf;

    // ldmatrix bases
    const uint32_t smb = s2u(sm);
    const uint32_t laA = (uint32_t)((lane & 15) + wm * 32) * ROW_S + (lane >> 4) * 16;
    const uint32_t lbB = G1_BOFF +
        (uint32_t)(wn * 16 + ((lane >> 4) & 1) * 8 + (lane & 7)) * ROW_S +
        ((lane >> 3) & 1) * 16;

    float cg[2][2][4] = {}, cl[2][2][4] = {};
    uint4 ra[2], rb[4];

#pragma unroll
    for (int q = 0; q < 2; q++) ra[q] = *(const uint4*)(srcA + q * 16);
#pragma unroll
    for (int q = 0; q < 4; q++) rb[q] = *(const uint4*)(srcB + q * 16);

    for (int kt = 0; kt < NK1; kt++) {
        char* bb = sm + (kt & 1) * G1_STG;
#pragma unroll
        for (int q = 0; q < 2; q++) *(uint4*)(bb + dAo + q * 16) = ra[q];
#pragma unroll
        for (int q = 0; q < 4; q++) *(uint4*)(bb + dBo + q * 16) = rb[q];

        if (kt + 1 < NK1) {
            const unsigned char* sa = srcA + (size_t)(kt + 1) * 128;
            const unsigned char* sb = srcB + (size_t)(kt + 1) * 128;
#pragma unroll
            for (int q = 0; q < 2; q++) ra[q] = *(const uint4*)(sa + q * 16);
#pragma unroll
            for (int q = 0; q < 4; q++) rb[q] = *(const uint4*)(sb + q * 16);
        }

        // interleaved w2 conversion: independent, fills latency bubbles
        if (doCvt) {
            const int i4 = cvtBase + kt * 256;
            float4 v = ((const float4*)w2)[i4];
            ((uint2*)g_w2h)[i4] = cvt4(v);
        }
        __syncthreads();

        const uint32_t bbu = smb + (kt & 1) * G1_STG;
#pragma unroll
        for (int kk = 0; kk < 4; kk++) {
            uint32_t ah[2][4];
#pragma unroll
            for (int i = 0; i < 2; i++)
                ldsm4(ah[i], bbu + laA + i * (16 * ROW_S) + kk * 32);
            uint32_t bg4[4], bl4[4];
            ldsm4(bg4, bbu + lbB + kk * 32);
            ldsm4(bl4, bbu + lbB + 64 * ROW_S + kk * 32);
#pragma unroll
            for (int i = 0; i < 2; i++) {
                mma16816(cg[i][0], ah[i], &bg4[0]);
                mma16816(cg[i][1], ah[i], &bg4[2]);
                mma16816(cl[i][0], ah[i], &bl4[0]);
                mma16816(cl[i][1], ah[i], &bl4[2]);
            }
        }
        __syncthreads();
    }

    // epilogue: bias + silu(gate)*lin; store act as fp16 pairs
#pragma unroll
    for (int i = 0; i < 2; i++)
#pragma unroll
        for (int rr = 0; rr < 2; rr++) {
            const int m = wm * 32 + i * 16 + (lane >> 2) + rr * 8 + m0;
            if (m >= cnt) continue;
            __half* actrow = g_acth + (size_t)(off + m) * FF;
#pragma unroll
            for (int j = 0; j < 2; j++) {
                const int c = wn * 16 + j * 8 + (lane & 3) * 2;
                float r0, r1;
#pragma unroll
                for (int q = 0; q < 2; q++) {
                    const int idx = rr * 2 + q;
                    const float g = cg[i][j][idx] + s_bg[c + q];
                    const float l = cl[i][j][idx] + s_bl[c + q];
                    const float r = g * l / (1.0f + __expf(-g));
                    if (q == 0) r0 = r; else r1 = r;
                }
                __half2 hv = __floats2half2_rn(r0, r1);
                *(uint32_t*)(actrow + n0 + c) = *(uint32_t*)&hv;
            }
        }
}

// ---------------- GEMM2: out += scale*(act*W2^T + b2) ----------------------
// CTA: M=64, N=128 over H, k-chunk=64, 256 threads (8 warps 2Mx4N). (R14)
#define G2_BOFF (64 * ROW_S)               // 9216
#define G2_STG  (G2_BOFF + 128 * ROW_S)    // 27648 per stage

__global__ __launch_bounds__(256, 2)
void gemm2_kernel(const float* __restrict__ b2, float* __restrict__ out) {
    const int e   = blockIdx.y;
    const int cnt = g_count[e];
    const int m0  = blockIdx.z * 64;
    if (m0 >= cnt) return;
    const int n0  = blockIdx.x * 128;
    const int off = g_offset[e];

    extern __shared__ char sm[];
    __shared__ float s_b2[128];

    const int tid = threadIdx.x, lane = tid & 31, wid = tid >> 5;
    const int wm = wid & 1, wn = wid >> 1;

    if (tid < 128) s_b2[tid] = b2[(size_t)e * H + n0 + tid];

    // A staging: 64 rows x 128B; 4 thr/row x 32B
    const int arow = tid >> 2, acol = (tid & 3) * 32;
    const int mrow = m0 + arow;
    const unsigned char* srcA =
        (const unsigned char*)(g_acth +
            (size_t)(off + (mrow < cnt ? mrow : cnt - 1)) * FF) + acol;
    const uint32_t dAo = (uint32_t)arow * ROW_S + acol;

    // B staging: 128 rows x 128B; 2 thr/row x 64B
    const int brow = tid >> 1, bhalf = (tid & 1) * 64;
    const unsigned char* srcB =
        (const unsigned char*)(g_w2h + (size_t)(e * H + n0 + brow) * FF) + bhalf;
    const uint32_t dBo = G2_BOFF + (uint32_t)brow * ROW_S + bhalf;

    const uint32_t smb = s2u(sm);
    const uint32_t laA = (uint32_t)((lane & 15) + wm * 32) * ROW_S + (lane >> 4) * 16;
    const uint32_t lbB = G2_BOFF +
        (uint32_t)(wn * 32 + ((lane >> 4) & 1) * 8 + (lane & 7)) * ROW_S +
        ((lane >> 3) & 1) * 16;

    float c[2][4][4] = {};
    uint4 ra[2], rb[4];

#pragma unroll
    for (int q = 0; q < 2; q++) ra[q] = *(const uint4*)(srcA + q * 16);
#pragma unroll
    for (int q = 0; q < 4; q++) rb[q] = *(const uint4*)(srcB + q * 16);

    for (int kt = 0; kt < NK2; kt++) {
        char* bb = sm + (kt & 1) * G2_STG;
#pragma unroll
        for (int q = 0; q < 2; q++) *(uint4*)(bb + dAo + q * 16) = ra[q];
#pragma unroll
        for (int q = 0; q < 4; q++) *(uint4*)(bb + dBo + q * 16) = rb[q];

        if (kt + 1 < NK2) {
            const unsigned char* sa = srcA + (size_t)(kt + 1) * 128;
            const unsigned char* sb = srcB + (size_t)(kt + 1) * 128;
#pragma unroll
            for (int q = 0; q < 2; q++) ra[q] = *(const uint4*)(sa + q * 16);
#pragma unroll
            for (int q = 0; q < 4; q++) rb[q] = *(const uint4*)(sb + q * 16);
        }
        __syncthreads();

        const uint32_t bbu = smb + (kt & 1) * G2_STG;
#pragma unroll
        for (int kk = 0; kk < 4; kk++) {
            uint32_t ah[2][4];
#pragma unroll
            for (int i = 0; i < 2; i++)
                ldsm4(ah[i], bbu + laA + i * (16 * ROW_S) + kk * 32);
            uint32_t bhA[4], bhB[4];
            ldsm4(bhA, bbu + lbB + kk * 32);
            ldsm4(bhB, bbu + lbB + 16 * ROW_S + kk * 32);
#pragma unroll
            for (int i = 0; i < 2; i++) {
                mma16816(c[i][0], ah[i], &bhA[0]);
                mma16816(c[i][1], ah[i], &bhA[2]);
                mma16816(c[i][2], ah[i], &bhB[0]);
                mma16816(c[i][3], ah[i], &bhB[2]);
            }
        }
        __syncthreads();
    }

    // epilogue: scaled atomic scatter
#pragma unroll
    for (int i = 0; i < 2; i++)
#pragma unroll
        for (int rr = 0; rr < 2; rr++) {
            const int m = wm * 32 + i * 16 + (lane >> 2) + rr * 8 + m0;
            if (m >= cnt) continue;
            const int   sl  = off + m;
            const int   tok = g_tok[sl];
            const float sc  = g_scale[sl];
#pragma unroll
            for (int j = 0; j < 4; j++) {
                const int cc = wn * 32 + j * 8 + (lane & 3) * 2;
                atomicAdd(&out[(size_t)tok * H + n0 + cc],
                          sc * (c[i][j][rr * 2 + 0] + s_b2[cc]));
                atomicAdd(&out[(size_t)tok * H + n0 + cc + 1],
                          sc * (c[i][j][rr * 2 + 1] + s_b2[cc + 1]));
            }
        }
}

// ---------------- launch ----------------
extern "C" void kernel_launch(void* const* d_in, const int* in_sizes, int n_in,
                              void* d_out, int out_size) {
    const float* hidden = (const float*)d_in[0];
    const int*   sel    = (const int*)d_in[1];
    const float* scales = (const float*)d_in[2];
    const float* w1     = (const float*)d_in[3];
    const float* b1     = (const float*)d_in[4];
    const float* w2     = (const float*)d_in[5];
    const float* b2     = (const float*)d_in[6];

    void *p_hh, *p_w1h;
    cudaGetSymbolAddress(&p_hh,  g_hh);
    cudaGetSymbolAddress(&p_w1h, g_w1h);

    const int smem1 = 2 * G1_STG;   // 55296
    const int smem2 = 2 * G2_STG;   // 55296
    cudaFuncSetAttribute(gemm1_kernel, cudaFuncAttributeMaxDynamicSharedMemorySize, smem1);
    cudaFuncSetAttribute(gemm2_kernel, cudaFuncAttributeMaxDynamicSharedMemorySize, smem2);

    cudaMemsetAsync(d_out, 0, (size_t)T * H * sizeof(float), 0);

    route_prep<<<E + PREP_BLOCKS, 256>>>(sel, scales, hidden, w1,
                                         (__half*)p_hh, (__half*)p_w1h);

    dim3 g1(FF / 64, E, NSLOT / 64);    // 32 x 8 x 32
    gemm1_kernel<<<g1, 256, smem1>>>(b1, w2);

    dim3 g2(H / 128, E, NSLOT / 64);    // 8 x 8 x 32
    gemm2_kernel<<<g2, 256, smem2>>>(b2, (float*)d_out);
}